// round 1
// baseline (speedup 1.0000x reference)
#include <cuda_runtime.h>
#include <cmath>

// Problem shape (fixed)
#define NPAIR 65536
#define NPRED 1024
#define EMBD  1024

// Scratch: G = emb @ emb^T  (1024x1024 f32 = 4MB), emb row norms.
__device__ float g_G[NPRED * NPRED];
__device__ float g_embnorm[NPRED];

// ---------------------------------------------------------------------------
// emb row norms: one block per row
// ---------------------------------------------------------------------------
__global__ void emb_norm_kernel(const float* __restrict__ emb) {
    int j = blockIdx.x;
    const float4* row = reinterpret_cast<const float4*>(emb + (size_t)j * EMBD);
    float s = 0.f;
    for (int t = threadIdx.x; t < EMBD / 4; t += blockDim.x) {
        float4 v = row[t];
        s += v.x * v.x + v.y * v.y + v.z * v.z + v.w * v.w;
    }
    #pragma unroll
    for (int off = 16; off > 0; off >>= 1)
        s += __shfl_down_sync(0xffffffffu, s, off);
    __shared__ float ws[8];
    int lane = threadIdx.x & 31, wid = threadIdx.x >> 5;
    if (lane == 0) ws[wid] = s;
    __syncthreads();
    if (threadIdx.x == 0) {
        float tot = 0.f;
        #pragma unroll
        for (int w = 0; w < 8; w++) tot += ws[w];
        g_embnorm[j] = sqrtf(tot);
    }
}

// ---------------------------------------------------------------------------
// 128x128x8 fp32 SGEMM, C = A * B  (A: MxK row-major; B: KxN row-major, or
// TRANS_B: logical B[k][n] = Braw[n*K + k], i.e. C = A * Braw^T).
// 256 threads, 8x8 micro-tile per thread. K, M, N all multiples of tile dims.
// ---------------------------------------------------------------------------
template <bool TRANS_B>
__global__ __launch_bounds__(256, 2)
void sgemm128(const float* __restrict__ A, const float* __restrict__ B,
              float* __restrict__ C, int M, int N, int K) {
    __shared__ float As[8][128];   // As[k][m]
    __shared__ float Bs[8][128];   // Bs[k][n]

    const int tid = threadIdx.x;
    const int tx = tid & 15;   // 0..15 -> col group (8 cols each)
    const int ty = tid >> 4;   // 0..15 -> row group (8 rows each)
    const int m0 = blockIdx.y * 128;
    const int n0 = blockIdx.x * 128;

    // A tile loader: 128 rows x 8 cols, one float4 per thread, transposed store
    const int arow = tid >> 1;        // 0..127
    const int acol = (tid & 1) * 4;   // 0 or 4
    // B tile loader (non-trans): 8 rows x 128 cols, one float4 per thread
    const int brow = tid >> 5;        // 0..7
    const int bcol = (tid & 31) * 4;  // 0..124

    float acc[8][8];
    #pragma unroll
    for (int i = 0; i < 8; i++)
        #pragma unroll
        for (int j = 0; j < 8; j++) acc[i][j] = 0.f;

    const float* Aptr  = A + (size_t)(m0 + arow) * K + acol;
    const float* BptrT = B + (size_t)(n0 + arow) * K + acol;        // trans: reuse arow as n
    const float* BptrN = B + (size_t)brow * N + n0 + bcol;

    for (int k0 = 0; k0 < K; k0 += 8) {
        float4 av = *reinterpret_cast<const float4*>(Aptr + k0);
        As[acol + 0][arow] = av.x;
        As[acol + 1][arow] = av.y;
        As[acol + 2][arow] = av.z;
        As[acol + 3][arow] = av.w;
        if (TRANS_B) {
            float4 bv = *reinterpret_cast<const float4*>(BptrT + k0);
            Bs[acol + 0][arow] = bv.x;
            Bs[acol + 1][arow] = bv.y;
            Bs[acol + 2][arow] = bv.z;
            Bs[acol + 3][arow] = bv.w;
        } else {
            float4 bv = *reinterpret_cast<const float4*>(BptrN + (size_t)k0 * N);
            *reinterpret_cast<float4*>(&Bs[brow][bcol]) = bv;
        }
        __syncthreads();

        #pragma unroll
        for (int kk = 0; kk < 8; kk++) {
            float4 a0 = *reinterpret_cast<const float4*>(&As[kk][ty * 8]);
            float4 a1 = *reinterpret_cast<const float4*>(&As[kk][ty * 8 + 4]);
            float4 b0 = *reinterpret_cast<const float4*>(&Bs[kk][tx * 8]);
            float4 b1 = *reinterpret_cast<const float4*>(&Bs[kk][tx * 8 + 4]);
            float a[8] = {a0.x, a0.y, a0.z, a0.w, a1.x, a1.y, a1.z, a1.w};
            float b[8] = {b0.x, b0.y, b0.z, b0.w, b1.x, b1.y, b1.z, b1.w};
            #pragma unroll
            for (int i = 0; i < 8; i++)
                #pragma unroll
                for (int j = 0; j < 8; j++)
                    acc[i][j] = fmaf(a[i], b[j], acc[i][j]);
        }
        __syncthreads();
    }

    #pragma unroll
    for (int i = 0; i < 8; i++) {
        float* crow = C + (size_t)(m0 + ty * 8 + i) * N + n0 + tx * 8;
        float4 c0 = {acc[i][0], acc[i][1], acc[i][2], acc[i][3]};
        float4 c1 = {acc[i][4], acc[i][5], acc[i][6], acc[i][7]};
        *reinterpret_cast<float4*>(crow) = c0;
        *reinterpret_cast<float4*>(crow + 4) = c1;
    }
}

// ---------------------------------------------------------------------------
// Epilogue: per row i, s = sum_j D[i][j] * x[i][j]  (= ||x_i E||^2),
// then out[i][j] = D[i][j] / max(sqrt(s) * embnorm[j], 1e-8). In-place on out.
// One block of 256 threads per row; each thread owns one float4 (1024/4/256).
// ---------------------------------------------------------------------------
__global__ void normalize_kernel(const float* __restrict__ x, float* __restrict__ out) {
    const int i = blockIdx.x;
    const int t = threadIdx.x;  // 0..255
    float4* drow = reinterpret_cast<float4*>(out + (size_t)i * NPRED);
    const float4* xrow = reinterpret_cast<const float4*>(x + (size_t)i * NPRED);

    float4 d = drow[t];
    float4 xv = xrow[t];
    float s = d.x * xv.x + d.y * xv.y + d.z * xv.z + d.w * xv.w;

    #pragma unroll
    for (int off = 16; off > 0; off >>= 1)
        s += __shfl_down_sync(0xffffffffu, s, off);

    __shared__ float ws[8];
    __shared__ float snorm_sh;
    if ((t & 31) == 0) ws[t >> 5] = s;
    __syncthreads();
    if (t == 0) {
        float tot = 0.f;
        #pragma unroll
        for (int w = 0; w < 8; w++) tot += ws[w];
        snorm_sh = sqrtf(tot);
    }
    __syncthreads();

    const float sn = snorm_sh;
    float4 en = reinterpret_cast<const float4*>(g_embnorm)[t];
    float4 o;
    o.x = d.x / fmaxf(sn * en.x, 1e-8f);
    o.y = d.y / fmaxf(sn * en.y, 1e-8f);
    o.z = d.z / fmaxf(sn * en.z, 1e-8f);
    o.w = d.w / fmaxf(sn * en.w, 1e-8f);
    drow[t] = o;
}

// ---------------------------------------------------------------------------
extern "C" void kernel_launch(void* const* d_in, const int* in_sizes, int n_in,
                              void* d_out, int out_size) {
    const float* x   = (const float*)d_in[0];   // [1, 65536, 1024] f32
    const float* emb = (const float*)d_in[1];   // [1024, 1024] f32
    float* out = (float*)d_out;                 // [1, 65536, 1024] f32

    float* Gptr = nullptr;
    cudaGetSymbolAddress((void**)&Gptr, g_G);

    // 1) emb row norms
    emb_norm_kernel<<<NPRED, 256>>>(emb);

    // 2) G = emb @ emb^T   (M=N=K=1024)
    {
        dim3 grid(NPRED / 128, NPRED / 128);
        sgemm128<true><<<grid, 256>>>(emb, emb, Gptr, NPRED, NPRED, EMBD);
    }

    // 3) D = x @ G  -> d_out   (M=65536, N=1024, K=1024)
    {
        dim3 grid(NPRED / 128, NPAIR / 128);
        sgemm128<false><<<grid, 256>>>(x, Gptr, out, NPAIR, NPRED, NPRED);
    }

    // 4) cosine normalize in-place
    normalize_kernel<<<NPAIR, 256>>>(x, out);
}

// round 4
// speedup vs baseline: 2.6912x; 2.6912x over previous
#include <cuda_runtime.h>
#include <cuda_fp16.h>
#include <cstdint>
#include <cmath>

// Problem shape (fixed)
#define NPAIR 65536
#define NPRED 1024
#define EMBD  1024

// ---------------------------------------------------------------------------
// Device scratch (static — no runtime allocation)
// ---------------------------------------------------------------------------
__device__ float  g_G[NPRED * NPRED];            // 4 MB   G = E E^T (f32)
__device__ __half g_ghi[NPRED * NPRED];          // 2 MB
__device__ __half g_glo[NPRED * NPRED];          // 2 MB
__device__ __half g_xh[(size_t)NPAIR * NPRED];   // 128 MB  x in fp16
__device__ float  g_embnorm[NPRED];

// ---------------------------------------------------------------------------
// PTX helpers (baseline ISA only: cp.async / ldmatrix / mma.sync)
// ---------------------------------------------------------------------------
__device__ __forceinline__ uint32_t smem_u32(const void* p) {
    uint32_t a;
    asm("{ .reg .u64 t; cvta.to.shared.u64 t, %1; cvt.u32.u64 %0, t; }" : "=r"(a) : "l"(p));
    return a;
}
#define CP_ASYNC16(dst_u32, src_ptr) \
    asm volatile("cp.async.cg.shared.global [%0], [%1], 16;\n" :: "r"(dst_u32), "l"(src_ptr))
#define CP_COMMIT() asm volatile("cp.async.commit_group;\n" ::: "memory")
#define CP_WAIT(n)  asm volatile("cp.async.wait_group %0;\n" :: "n"(n) : "memory")

#define LDSM_X4(r0, r1, r2, r3, addr) \
    asm volatile("ldmatrix.sync.aligned.m8n8.x4.shared.b16 {%0,%1,%2,%3}, [%4];" \
                 : "=r"(r0), "=r"(r1), "=r"(r2), "=r"(r3) : "r"(addr))

#define MMA16816(c, a, b0, b1) \
    asm volatile("mma.sync.aligned.m16n8k16.row.col.f32.f16.f16.f32 " \
                 "{%0,%1,%2,%3}, {%4,%5,%6,%7}, {%8,%9}, {%0,%1,%2,%3};" \
                 : "+f"((c)[0]), "+f"((c)[1]), "+f"((c)[2]), "+f"((c)[3]) \
                 : "r"((a)[0]), "r"((a)[1]), "r"((a)[2]), "r"((a)[3]), "r"(b0), "r"(b1))

// ---------------------------------------------------------------------------
// x (f32) -> fp16
// ---------------------------------------------------------------------------
__global__ void convert_x_kernel(const float* __restrict__ x, __half* __restrict__ xh) {
    size_t base = ((size_t)blockIdx.x * 256 + threadIdx.x) * 8;
    float4 a = *reinterpret_cast<const float4*>(x + base);
    float4 b = *reinterpret_cast<const float4*>(x + base + 4);
    float v[8] = {a.x, a.y, a.z, a.w, b.x, b.y, b.z, b.w};
    __half h[8];
    #pragma unroll
    for (int i = 0; i < 8; i++) h[i] = __float2half_rn(v[i]);
    *reinterpret_cast<uint4*>(xh + base) = *reinterpret_cast<uint4*>(h);
}

// G (f32) -> fp16 hi + lo
__global__ void convert_g_kernel(const float* __restrict__ G,
                                 __half* __restrict__ ghi, __half* __restrict__ glo) {
    size_t base = ((size_t)blockIdx.x * 256 + threadIdx.x) * 8;
    float4 a = *reinterpret_cast<const float4*>(G + base);
    float4 b = *reinterpret_cast<const float4*>(G + base + 4);
    float v[8] = {a.x, a.y, a.z, a.w, b.x, b.y, b.z, b.w};
    __half hi[8], lo[8];
    #pragma unroll
    for (int i = 0; i < 8; i++) {
        hi[i] = __float2half_rn(v[i]);
        lo[i] = __float2half_rn(v[i] - __half2float(hi[i]));
    }
    *reinterpret_cast<uint4*>(ghi + base) = *reinterpret_cast<uint4*>(hi);
    *reinterpret_cast<uint4*>(glo + base) = *reinterpret_cast<uint4*>(lo);
}

// emb row norms from diag(G)
__global__ void diag_norm_kernel(const float* __restrict__ G) {
    int j = blockIdx.x * 256 + threadIdx.x;
    if (j < NPRED) g_embnorm[j] = sqrtf(G[(size_t)j * (NPRED + 1)]);
}

// ---------------------------------------------------------------------------
// fp32 SGEMM for G = E E^T (small, 2.1 GF)
// ---------------------------------------------------------------------------
__global__ __launch_bounds__(256, 2)
void sgemm_g(const float* __restrict__ A, float* __restrict__ C, int M, int N, int K) {
    __shared__ float As[8][128];
    __shared__ float Bs[8][128];
    const int tid = threadIdx.x;
    const int tx = tid & 15, ty = tid >> 4;
    const int m0 = blockIdx.y * 128, n0 = blockIdx.x * 128;
    const int arow = tid >> 1, acol = (tid & 1) * 4;
    float acc[8][8];
    #pragma unroll
    for (int i = 0; i < 8; i++)
        #pragma unroll
        for (int j = 0; j < 8; j++) acc[i][j] = 0.f;
    const float* Aptr  = A + (size_t)(m0 + arow) * K + acol;
    const float* BptrT = A + (size_t)(n0 + arow) * K + acol;
    for (int k0 = 0; k0 < K; k0 += 8) {
        float4 av = *reinterpret_cast<const float4*>(Aptr + k0);
        As[acol + 0][arow] = av.x; As[acol + 1][arow] = av.y;
        As[acol + 2][arow] = av.z; As[acol + 3][arow] = av.w;
        float4 bv = *reinterpret_cast<const float4*>(BptrT + k0);
        Bs[acol + 0][arow] = bv.x; Bs[acol + 1][arow] = bv.y;
        Bs[acol + 2][arow] = bv.z; Bs[acol + 3][arow] = bv.w;
        __syncthreads();
        #pragma unroll
        for (int kk = 0; kk < 8; kk++) {
            float4 a0 = *reinterpret_cast<const float4*>(&As[kk][ty * 8]);
            float4 a1 = *reinterpret_cast<const float4*>(&As[kk][ty * 8 + 4]);
            float4 b0 = *reinterpret_cast<const float4*>(&Bs[kk][tx * 8]);
            float4 b1 = *reinterpret_cast<const float4*>(&Bs[kk][tx * 8 + 4]);
            float a[8] = {a0.x, a0.y, a0.z, a0.w, a1.x, a1.y, a1.z, a1.w};
            float b[8] = {b0.x, b0.y, b0.z, b0.w, b1.x, b1.y, b1.z, b1.w};
            #pragma unroll
            for (int i = 0; i < 8; i++)
                #pragma unroll
                for (int j = 0; j < 8; j++)
                    acc[i][j] = fmaf(a[i], b[j], acc[i][j]);
        }
        __syncthreads();
    }
    #pragma unroll
    for (int i = 0; i < 8; i++) {
        float* crow = C + (size_t)(m0 + ty * 8 + i) * N + n0 + tx * 8;
        float4 c0 = {acc[i][0], acc[i][1], acc[i][2], acc[i][3]};
        float4 c1 = {acc[i][4], acc[i][5], acc[i][6], acc[i][7]};
        *reinterpret_cast<float4*>(crow) = c0;
        *reinterpret_cast<float4*>(crow + 4) = c1;
    }
}

// ---------------------------------------------------------------------------
// Main HMMA GEMM:  D = Xh * Ghi^T + Xh * Glo^T   (G symmetric -> rows are B)
// CTA 128x128, BK=32, 4-stage cp.async pipeline, 8 warps (32x64 each).
// SMEM rows padded to 80B (20 words) -> ldmatrix conflict-free, no swizzle.
// ---------------------------------------------------------------------------
#define BK 32
#define ROW_B 80                     // bytes per smem row (32 halfs + 8 pad)
#define TILE_B (128 * ROW_B)         // 10240
#define STAGE_B (3 * TILE_B)         // A, Bhi, Blo
#define NSTAGE 4
#define SMEM_MM (NSTAGE * STAGE_B)   // 122880
#define NKSTEP (NPRED / BK)          // 32

__device__ __forceinline__ void load_tile(uint32_t s_tile, const __half* src,
                                          int row0, int k0, int tid) {
    #pragma unroll
    for (int i = 0; i < 2; i++) {
        int idx = i * 256 + tid;
        int row = idx >> 2;
        int ch  = idx & 3;
        const char* g = reinterpret_cast<const char*>(src + (size_t)(row0 + row) * NPRED + k0)
                        + ch * 16;
        uint32_t s = s_tile + row * ROW_B + ch * 16;
        CP_ASYNC16(s, g);
    }
}

__global__ __launch_bounds__(256, 1)
void mm_hmma(const __half* __restrict__ xh, const __half* __restrict__ ghi,
             const __half* __restrict__ glo, float* __restrict__ out) {
    extern __shared__ char smem[];
    const uint32_t sbase = smem_u32(smem);
    const int tid  = threadIdx.x;
    const int wid  = tid >> 5;
    const int lane = tid & 31;
    const int n0 = blockIdx.x * 128;   // x fast => 8 CTAs share A slice in L2
    const int m0 = blockIdx.y * 128;

    const int wm = wid & 3;    // 0..3  -> 32-row slice
    const int wn = wid >> 2;   // 0..1  -> 64-col slice

    // ldmatrix lane address components (within a tile)
    const int aRow = wm * 32 + (lane & 15);
    const int aColB = ((lane >> 4) * 8) * 2;
    const uint32_t a_off = aRow * ROW_B + aColB;
    const int bRow = wn * 64 + (lane & 7) + ((lane >> 4) << 3);
    const int bColB = (((lane >> 3) & 1) * 8) * 2;
    const uint32_t b_off = bRow * ROW_B + bColB;

    float acc[2][8][4];
    #pragma unroll
    for (int i = 0; i < 2; i++)
        #pragma unroll
        for (int j = 0; j < 8; j++)
            #pragma unroll
            for (int q = 0; q < 4; q++) acc[i][j][q] = 0.f;

    // prologue: stages 0..2
    #pragma unroll
    for (int s = 0; s < NSTAGE - 1; s++) {
        uint32_t stg = sbase + s * STAGE_B;
        load_tile(stg + 0 * TILE_B, xh,  m0, s * BK, tid);
        load_tile(stg + 1 * TILE_B, ghi, n0, s * BK, tid);
        load_tile(stg + 2 * TILE_B, glo, n0, s * BK, tid);
        CP_COMMIT();
    }

    for (int s = 0; s < NKSTEP; s++) {
        if (s + NSTAGE - 1 < NKSTEP) {
            uint32_t stg = sbase + ((s + NSTAGE - 1) & (NSTAGE - 1)) * STAGE_B;
            int k0 = (s + NSTAGE - 1) * BK;
            load_tile(stg + 0 * TILE_B, xh,  m0, k0, tid);
            load_tile(stg + 1 * TILE_B, ghi, n0, k0, tid);
            load_tile(stg + 2 * TILE_B, glo, n0, k0, tid);
        }
        CP_COMMIT();
        CP_WAIT(NSTAGE - 1);
        __syncthreads();

        uint32_t stg = sbase + (s & (NSTAGE - 1)) * STAGE_B;
        uint32_t sA  = stg + a_off;
        uint32_t sBh = stg + 1 * TILE_B + b_off;
        uint32_t sBl = stg + 2 * TILE_B + b_off;

        #pragma unroll
        for (int kk = 0; kk < 2; kk++) {
            uint32_t a[2][4];
            #pragma unroll
            for (int i = 0; i < 2; i++)
                LDSM_X4(a[i][0], a[i][1], a[i][2], a[i][3],
                        sA + i * (16 * ROW_B) + kk * 32);
            uint32_t bh[4][4], bl[4][4];
            #pragma unroll
            for (int j = 0; j < 4; j++) {
                LDSM_X4(bh[j][0], bh[j][1], bh[j][2], bh[j][3],
                        sBh + j * (16 * ROW_B) + kk * 32);
                LDSM_X4(bl[j][0], bl[j][1], bl[j][2], bl[j][3],
                        sBl + j * (16 * ROW_B) + kk * 32);
            }
            #pragma unroll
            for (int i = 0; i < 2; i++)
                #pragma unroll
                for (int j = 0; j < 4; j++) {
                    MMA16816(acc[i][j * 2 + 0], a[i], bh[j][0], bh[j][1]);
                    MMA16816(acc[i][j * 2 + 0], a[i], bl[j][0], bl[j][1]);
                    MMA16816(acc[i][j * 2 + 1], a[i], bh[j][2], bh[j][3]);
                    MMA16816(acc[i][j * 2 + 1], a[i], bl[j][2], bl[j][3]);
                }
        }
        __syncthreads();
    }

    // epilogue: float2 stores
    #pragma unroll
    for (int i = 0; i < 2; i++) {
        #pragma unroll
        for (int j8 = 0; j8 < 8; j8++) {
            int r = m0 + wm * 32 + i * 16 + (lane >> 2);
            int c = n0 + wn * 64 + j8 * 8 + (lane & 3) * 2;
            float2 v0 = {acc[i][j8][0], acc[i][j8][1]};
            float2 v1 = {acc[i][j8][2], acc[i][j8][3]};
            *reinterpret_cast<float2*>(out + (size_t)r * NPRED + c) = v0;
            *reinterpret_cast<float2*>(out + (size_t)(r + 8) * NPRED + c) = v1;
        }
    }
}

// ---------------------------------------------------------------------------
// Cosine normalize in-place:  s = sum_j D[i][j] x[i][j] = ||x_i E||^2
// ---------------------------------------------------------------------------
__global__ void normalize_kernel(const float* __restrict__ x, float* __restrict__ out) {
    const int i = blockIdx.x;
    const int t = threadIdx.x;
    float4* drow = reinterpret_cast<float4*>(out + (size_t)i * NPRED);
    const float4* xrow = reinterpret_cast<const float4*>(x + (size_t)i * NPRED);

    float4 d = drow[t];
    float4 xv = xrow[t];
    float s = d.x * xv.x + d.y * xv.y + d.z * xv.z + d.w * xv.w;
    #pragma unroll
    for (int off = 16; off > 0; off >>= 1)
        s += __shfl_down_sync(0xffffffffu, s, off);
    __shared__ float ws[8];
    __shared__ float snorm_sh;
    if ((t & 31) == 0) ws[t >> 5] = s;
    __syncthreads();
    if (t == 0) {
        float tot = 0.f;
        #pragma unroll
        for (int w = 0; w < 8; w++) tot += ws[w];
        snorm_sh = sqrtf(tot);
    }
    __syncthreads();
    const float sn = snorm_sh;
    float4 en = reinterpret_cast<const float4*>(g_embnorm)[t];
    float4 o;
    o.x = d.x / fmaxf(sn * en.x, 1e-8f);
    o.y = d.y / fmaxf(sn * en.y, 1e-8f);
    o.z = d.z / fmaxf(sn * en.z, 1e-8f);
    o.w = d.w / fmaxf(sn * en.w, 1e-8f);
    drow[t] = o;
}

// ---------------------------------------------------------------------------
extern "C" void kernel_launch(void* const* d_in, const int* in_sizes, int n_in,
                              void* d_out, int out_size) {
    const float* x   = (const float*)d_in[0];   // [1, 65536, 1024]
    const float* emb = (const float*)d_in[1];   // [1024, 1024]
    float* out = (float*)d_out;

    float* Gp;
    __half *ghip, *glop, *xhp;
    cudaGetSymbolAddress((void**)&Gp, g_G);
    cudaGetSymbolAddress((void**)&ghip, g_ghi);
    cudaGetSymbolAddress((void**)&glop, g_glo);
    cudaGetSymbolAddress((void**)&xhp, g_xh);

    cudaFuncSetAttribute(mm_hmma, cudaFuncAttributeMaxDynamicSharedMemorySize, SMEM_MM);

    // 1) x -> fp16
    convert_x_kernel<<<(size_t)NPAIR * NPRED / (256 * 8), 256>>>(x, xhp);

    // 2) G = E E^T (f32), split to fp16 hi/lo, diag norms
    {
        dim3 grid(NPRED / 128, NPRED / 128);
        sgemm_g<<<grid, 256>>>(emb, Gp, NPRED, NPRED, EMBD);
    }
    convert_g_kernel<<<NPRED * NPRED / (256 * 8), 256>>>(Gp, ghip, glop);
    diag_norm_kernel<<<NPRED / 256, 256>>>(Gp);

    // 3) D = x G  via HMMA (2-term fp16)  -> d_out
    {
        dim3 grid(NPRED / 128, NPAIR / 128);
        mm_hmma<<<grid, 256, SMEM_MM>>>(xhp, ghip, glop, out);
    }

    // 4) cosine normalize in-place
    normalize_kernel<<<NPAIR, 256>>>(x, out);
}

// round 17
// speedup vs baseline: 4.0976x; 1.5226x over previous
#include <cuda_runtime.h>
#include <cuda_fp16.h>
#include <cstdint>
#include <cmath>

// Problem shape (fixed)
#define NPAIR 65536
#define NPRED 1024
#define EMBD  1024

// ---------------------------------------------------------------------------
// Device scratch (static — no runtime allocation)
// ---------------------------------------------------------------------------
__device__ float  g_G[NPRED * NPRED];            // 4 MB   G = E E^T (f32)
__device__ __half g_ghi[NPRED * NPRED];          // 2 MB   G in fp16
__device__ __half g_xh[(size_t)NPAIR * NPRED];   // 128 MB x in fp16
__device__ float  g_embnorm[NPRED];

// ---------------------------------------------------------------------------
// PTX helpers (baseline ISA only: cp.async / ldmatrix / mma.sync)
// ---------------------------------------------------------------------------
__device__ __forceinline__ uint32_t smem_u32(const void* p) {
    uint32_t a;
    asm("{ .reg .u64 t; cvta.to.shared.u64 t, %1; cvt.u32.u64 %0, t; }" : "=r"(a) : "l"(p));
    return a;
}
#define CP_ASYNC16(dst_u32, src_ptr) \
    asm volatile("cp.async.cg.shared.global [%0], [%1], 16;\n" :: "r"(dst_u32), "l"(src_ptr))
#define CP_COMMIT() asm volatile("cp.async.commit_group;\n" ::: "memory")
#define CP_WAIT(n)  asm volatile("cp.async.wait_group %0;\n" :: "n"(n) : "memory")

#define LDSM_X4(r0, r1, r2, r3, addr) \
    asm volatile("ldmatrix.sync.aligned.m8n8.x4.shared.b16 {%0,%1,%2,%3}, [%4];" \
                 : "=r"(r0), "=r"(r1), "=r"(r2), "=r"(r3) : "r"(addr))

#define MMA16816(c, a, b0, b1) \
    asm volatile("mma.sync.aligned.m16n8k16.row.col.f32.f16.f16.f32 " \
                 "{%0,%1,%2,%3}, {%4,%5,%6,%7}, {%8,%9}, {%0,%1,%2,%3};" \
                 : "+f"((c)[0]), "+f"((c)[1]), "+f"((c)[2]), "+f"((c)[3]) \
                 : "r"((a)[0]), "r"((a)[1]), "r"((a)[2]), "r"((a)[3]), "r"(b0), "r"(b1))

// ---------------------------------------------------------------------------
// x (f32) -> fp16
// ---------------------------------------------------------------------------
__global__ void convert_x_kernel(const float* __restrict__ x, __half* __restrict__ xh) {
    size_t base = ((size_t)blockIdx.x * 256 + threadIdx.x) * 8;
    float4 a = *reinterpret_cast<const float4*>(x + base);
    float4 b = *reinterpret_cast<const float4*>(x + base + 4);
    float v[8] = {a.x, a.y, a.z, a.w, b.x, b.y, b.z, b.w};
    __half h[8];
    #pragma unroll
    for (int i = 0; i < 8; i++) h[i] = __float2half_rn(v[i]);
    *reinterpret_cast<uint4*>(xh + base) = *reinterpret_cast<uint4*>(h);
}

// G (f32) -> fp16
__global__ void convert_g_kernel(const float* __restrict__ G, __half* __restrict__ ghi) {
    size_t base = ((size_t)blockIdx.x * 256 + threadIdx.x) * 8;
    float4 a = *reinterpret_cast<const float4*>(G + base);
    float4 b = *reinterpret_cast<const float4*>(G + base + 4);
    float v[8] = {a.x, a.y, a.z, a.w, b.x, b.y, b.z, b.w};
    __half h[8];
    #pragma unroll
    for (int i = 0; i < 8; i++) h[i] = __float2half_rn(v[i]);
    *reinterpret_cast<uint4*>(ghi + base) = *reinterpret_cast<uint4*>(h);
}

// emb row norms from diag(G)
__global__ void diag_norm_kernel(const float* __restrict__ G) {
    int j = blockIdx.x * 256 + threadIdx.x;
    if (j < NPRED) g_embnorm[j] = sqrtf(G[(size_t)j * (NPRED + 1)]);
}

// ---------------------------------------------------------------------------
// fp32 SGEMM for G = E E^T.  64x128 tiles, 128 threads, 128 CTAs (one wave).
// ---------------------------------------------------------------------------
__global__ __launch_bounds__(128, 2)
void sgemm_g(const float* __restrict__ A, float* __restrict__ C, int M, int N, int K) {
    __shared__ float As[8][64];
    __shared__ float Bs[8][128];
    const int tid = threadIdx.x;
    const int tx = tid & 15, ty = tid >> 4;     // 16 x 8 thread grid
    const int m0 = blockIdx.y * 64, n0 = blockIdx.x * 128;
    const int arow = tid >> 1, acol = (tid & 1) * 4;   // 64 rows x 8 cols
    float acc[8][8];
    #pragma unroll
    for (int i = 0; i < 8; i++)
        #pragma unroll
        for (int j = 0; j < 8; j++) acc[i][j] = 0.f;
    const float* Aptr  = A + (size_t)(m0 + arow) * K + acol;
    const float* Bptr0 = A + (size_t)(n0 + arow) * K + acol;        // E rows as B (trans)
    const float* Bptr1 = A + (size_t)(n0 + 64 + arow) * K + acol;
    for (int k0 = 0; k0 < K; k0 += 8) {
        float4 av = *reinterpret_cast<const float4*>(Aptr + k0);
        As[acol + 0][arow] = av.x; As[acol + 1][arow] = av.y;
        As[acol + 2][arow] = av.z; As[acol + 3][arow] = av.w;
        float4 b0 = *reinterpret_cast<const float4*>(Bptr0 + k0);
        Bs[acol + 0][arow] = b0.x; Bs[acol + 1][arow] = b0.y;
        Bs[acol + 2][arow] = b0.z; Bs[acol + 3][arow] = b0.w;
        float4 b1 = *reinterpret_cast<const float4*>(Bptr1 + k0);
        Bs[acol + 0][arow + 64] = b1.x; Bs[acol + 1][arow + 64] = b1.y;
        Bs[acol + 2][arow + 64] = b1.z; Bs[acol + 3][arow + 64] = b1.w;
        __syncthreads();
        #pragma unroll
        for (int kk = 0; kk < 8; kk++) {
            float4 a0 = *reinterpret_cast<const float4*>(&As[kk][ty * 8]);
            float4 a1 = *reinterpret_cast<const float4*>(&As[kk][ty * 8 + 4]);
            float4 c0 = *reinterpret_cast<const float4*>(&Bs[kk][tx * 8]);
            float4 c1 = *reinterpret_cast<const float4*>(&Bs[kk][tx * 8 + 4]);
            float a[8] = {a0.x, a0.y, a0.z, a0.w, a1.x, a1.y, a1.z, a1.w};
            float b[8] = {c0.x, c0.y, c0.z, c0.w, c1.x, c1.y, c1.z, c1.w};
            #pragma unroll
            for (int i = 0; i < 8; i++)
                #pragma unroll
                for (int j = 0; j < 8; j++)
                    acc[i][j] = fmaf(a[i], b[j], acc[i][j]);
        }
        __syncthreads();
    }
    #pragma unroll
    for (int i = 0; i < 8; i++) {
        float* crow = C + (size_t)(m0 + ty * 8 + i) * N + n0 + tx * 8;
        float4 c0 = {acc[i][0], acc[i][1], acc[i][2], acc[i][3]};
        float4 c1 = {acc[i][4], acc[i][5], acc[i][6], acc[i][7]};
        *reinterpret_cast<float4*>(crow) = c0;
        *reinterpret_cast<float4*>(crow + 4) = c1;
    }
}

// ---------------------------------------------------------------------------
// Main HMMA GEMM:  D = Xh * Ghi^T   (G symmetric -> its rows are B operand)
// CTA 128x128, BK=32, 4-stage cp.async pipeline, 8 warps (32x64 each).
// SMEM rows padded to 80B (20 words) -> ldmatrix conflict-free, no swizzle.
// ---------------------------------------------------------------------------
#define BK 32
#define ROW_B 80                     // bytes per smem row (32 halfs + 8 pad)
#define TILE_B (128 * ROW_B)         // 10240
#define STAGE_B (2 * TILE_B)         // A, B
#define NSTAGE 4
#define SMEM_MM (NSTAGE * STAGE_B)   // 81920
#define NKSTEP (NPRED / BK)          // 32

__device__ __forceinline__ void load_tile(uint32_t s_tile, const __half* src,
                                          int row0, int k0, int tid) {
    #pragma unroll
    for (int i = 0; i < 2; i++) {
        int idx = i * 256 + tid;
        int row = idx >> 2;
        int ch  = idx & 3;
        const char* g = reinterpret_cast<const char*>(src + (size_t)(row0 + row) * NPRED + k0)
                        + ch * 16;
        uint32_t s = s_tile + row * ROW_B + ch * 16;
        CP_ASYNC16(s, g);
    }
}

__global__ __launch_bounds__(256, 1)
void mm_hmma(const __half* __restrict__ xh, const __half* __restrict__ ghi,
             float* __restrict__ out) {
    extern __shared__ char smem[];
    const uint32_t sbase = smem_u32(smem);
    const int tid  = threadIdx.x;
    const int wid  = tid >> 5;
    const int lane = tid & 31;
    const int n0 = blockIdx.x * 128;   // x fast => 8 CTAs share A slice in L2
    const int m0 = blockIdx.y * 128;

    const int wm = wid & 3;    // 0..3  -> 32-row slice
    const int wn = wid >> 2;   // 0..1  -> 64-col slice

    // ldmatrix lane address components (within a tile)
    const int aRow = wm * 32 + (lane & 15);
    const int aColB = ((lane >> 4) * 8) * 2;
    const uint32_t a_off = aRow * ROW_B + aColB;
    const int bRow = wn * 64 + (lane & 7) + ((lane >> 4) << 3);
    const int bColB = (((lane >> 3) & 1) * 8) * 2;
    const uint32_t b_off = bRow * ROW_B + bColB;

    float acc[2][8][4];
    #pragma unroll
    for (int i = 0; i < 2; i++)
        #pragma unroll
        for (int j = 0; j < 8; j++)
            #pragma unroll
            for (int q = 0; q < 4; q++) acc[i][j][q] = 0.f;

    // prologue: stages 0..2
    #pragma unroll
    for (int s = 0; s < NSTAGE - 1; s++) {
        uint32_t stg = sbase + s * STAGE_B;
        load_tile(stg + 0 * TILE_B, xh,  m0, s * BK, tid);
        load_tile(stg + 1 * TILE_B, ghi, n0, s * BK, tid);
        CP_COMMIT();
    }

    for (int s = 0; s < NKSTEP; s++) {
        if (s + NSTAGE - 1 < NKSTEP) {
            uint32_t stg = sbase + ((s + NSTAGE - 1) & (NSTAGE - 1)) * STAGE_B;
            int k0 = (s + NSTAGE - 1) * BK;
            load_tile(stg + 0 * TILE_B, xh,  m0, k0, tid);
            load_tile(stg + 1 * TILE_B, ghi, n0, k0, tid);
        }
        CP_COMMIT();
        CP_WAIT(NSTAGE - 1);
        __syncthreads();

        uint32_t stg = sbase + (s & (NSTAGE - 1)) * STAGE_B;
        uint32_t sA  = stg + a_off;
        uint32_t sB  = stg + 1 * TILE_B + b_off;

        #pragma unroll
        for (int kk = 0; kk < 2; kk++) {
            uint32_t a[2][4];
            #pragma unroll
            for (int i = 0; i < 2; i++)
                LDSM_X4(a[i][0], a[i][1], a[i][2], a[i][3],
                        sA + i * (16 * ROW_B) + kk * 32);
            uint32_t bh[4][4];
            #pragma unroll
            for (int j = 0; j < 4; j++)
                LDSM_X4(bh[j][0], bh[j][1], bh[j][2], bh[j][3],
                        sB + j * (16 * ROW_B) + kk * 32);
            #pragma unroll
            for (int i = 0; i < 2; i++)
                #pragma unroll
                for (int j = 0; j < 4; j++) {
                    MMA16816(acc[i][j * 2 + 0], a[i], bh[j][0], bh[j][1]);
                    MMA16816(acc[i][j * 2 + 1], a[i], bh[j][2], bh[j][3]);
                }
        }
        __syncthreads();
    }

    // epilogue: float2 stores
    #pragma unroll
    for (int i = 0; i < 2; i++) {
        #pragma unroll
        for (int j8 = 0; j8 < 8; j8++) {
            int r = m0 + wm * 32 + i * 16 + (lane >> 2);
            int c = n0 + wn * 64 + j8 * 8 + (lane & 3) * 2;
            float2 v0 = {acc[i][j8][0], acc[i][j8][1]};
            float2 v1 = {acc[i][j8][2], acc[i][j8][3]};
            *reinterpret_cast<float2*>(out + (size_t)r * NPRED + c) = v0;
            *reinterpret_cast<float2*>(out + (size_t)(r + 8) * NPRED + c) = v1;
        }
    }
}

// ---------------------------------------------------------------------------
// Cosine normalize in-place:  s = sum_j D[i][j] xh[i][j] = ||x_i E||^2
// (fp16 x is plenty for the norm; saves 128 MB of traffic vs f32 x)
// ---------------------------------------------------------------------------
__global__ void normalize_kernel(const __half* __restrict__ xh, float* __restrict__ out) {
    const int i = blockIdx.x;
    const int t = threadIdx.x;
    float4* drow = reinterpret_cast<float4*>(out + (size_t)i * NPRED);
    const __half2* xrow = reinterpret_cast<const __half2*>(xh + (size_t)i * NPRED);

    float4 d = drow[t];
    float2 xa = __half22float2(xrow[2 * t]);
    float2 xb = __half22float2(xrow[2 * t + 1]);
    float s = d.x * xa.x + d.y * xa.y + d.z * xb.x + d.w * xb.y;
    #pragma unroll
    for (int off = 16; off > 0; off >>= 1)
        s += __shfl_down_sync(0xffffffffu, s, off);
    __shared__ float ws[8];
    __shared__ float snorm_sh;
    if ((t & 31) == 0) ws[t >> 5] = s;
    __syncthreads();
    if (t == 0) {
        float tot = 0.f;
        #pragma unroll
        for (int w = 0; w < 8; w++) tot += ws[w];
        snorm_sh = sqrtf(tot);
    }
    __syncthreads();
    const float sn = snorm_sh;
    float4 en = reinterpret_cast<const float4*>(g_embnorm)[t];
    float4 o;
    o.x = d.x / fmaxf(sn * en.x, 1e-8f);
    o.y = d.y / fmaxf(sn * en.y, 1e-8f);
    o.z = d.z / fmaxf(sn * en.z, 1e-8f);
    o.w = d.w / fmaxf(sn * en.w, 1e-8f);
    drow[t] = o;
}

// ---------------------------------------------------------------------------
extern "C" void kernel_launch(void* const* d_in, const int* in_sizes, int n_in,
                              void* d_out, int out_size) {
    const float* x   = (const float*)d_in[0];   // [1, 65536, 1024]
    const float* emb = (const float*)d_in[1];   // [1024, 1024]
    float* out = (float*)d_out;

    float* Gp;
    __half *ghip, *xhp;
    cudaGetSymbolAddress((void**)&Gp, g_G);
    cudaGetSymbolAddress((void**)&ghip, g_ghi);
    cudaGetSymbolAddress((void**)&xhp, g_xh);

    cudaFuncSetAttribute(mm_hmma, cudaFuncAttributeMaxDynamicSharedMemorySize, SMEM_MM);

    // 1) x -> fp16
    convert_x_kernel<<<(size_t)NPAIR * NPRED / (256 * 8), 256>>>(x, xhp);

    // 2) G = E E^T (f32), round to fp16, diag norms
    {
        dim3 grid(NPRED / 128, NPRED / 64);   // 8 x 16 = 128 CTAs
        sgemm_g<<<grid, 128>>>(emb, Gp, NPRED, NPRED, EMBD);
    }
    convert_g_kernel<<<NPRED * NPRED / (256 * 8), 256>>>(Gp, ghip);
    diag_norm_kernel<<<NPRED / 256, 256>>>(Gp);

    // 3) D = x G  via HMMA (single fp16 term)  -> d_out
    {
        dim3 grid(NPRED / 128, NPAIR / 128);
        mm_hmma<<<grid, 256, SMEM_MM>>>(xhp, ghip, out);
    }

    // 4) cosine normalize in-place
    normalize_kernel<<<NPAIR, 256>>>(xhp, out);
}